// round 12
// baseline (speedup 1.0000x reference)
#include <cuda_runtime.h>
#include <cuda_bf16.h>
#include <cstdint>

static constexpr int NN = 50000;
static constexpr int EE = 800000;
static constexpr int SCAN_BLKS = (NN + 1023) / 1024;   // 49
static constexpr int NPAD = NN + 256;                  // >= SCAN_BLKS*1024

// ---------------- scratch (device globals; no allocation allowed) ----------
__device__ float g_h[NN * 128];
__device__ float g_agg[NN * 128];
__device__ float g_deg[NN];
__device__ float g_dinv[NN];
__device__ int   g_cnt[NPAD];
__device__ int   g_rank[EE];
__device__ int   g_rowptr[NPAD];
__device__ int2  g_csr[EE];
__device__ float g_stats[1024];
__device__ int   g_blksum[SCAN_BLKS];
__device__ int   g_blkoff[SCAN_BLKS];
__device__ __align__(16) __nv_bfloat16 g_wblk[81920];

__device__ __forceinline__ uint32_t smem_u32(const void* p) {
    uint32_t a;
    asm("{ .reg .u64 t; cvta.to.shared.u64 t, %1; cvt.u32.u64 %0, t; }" : "=r"(a) : "l"(p));
    return a;
}
__device__ __forceinline__ uint32_t packbf2(float x, float y) {
    __nv_bfloat162 p = __floats2bfloat162_rn(x, y);
    return *(uint32_t*)&p;
}

#define MMA_BF16(d, a, b) \
    asm volatile("mma.sync.aligned.m16n8k16.row.col.f32.bf16.bf16.f32 " \
        "{%0,%1,%2,%3}, {%4,%5,%6,%7}, {%8,%9}, {%0,%1,%2,%3};" \
        : "+f"((d)[0]), "+f"((d)[1]), "+f"((d)[2]), "+f"((d)[3]) \
        : "r"((a)[0]), "r"((a)[1]), "r"((a)[2]), "r"((a)[3]), "r"((b)[0]), "r"((b)[1]))
#define LDSM_X4(r0, r1, r2, r3, addr) \
    asm volatile("ldmatrix.sync.aligned.m8n8.x4.shared.b16 {%0,%1,%2,%3}, [%4];" \
        : "=r"(r0), "=r"(r1), "=r"(r2), "=r"(r3) : "r"(addr))

// ---------------- CSR build ------------------------------------------------
__global__ void k_init() {
    int i = blockIdx.x * 256 + threadIdx.x;
    if (i < NN) { g_deg[i] = 1.0f; }
    if (i < NPAD) g_cnt[i] = 0;
    if (i < 1024) g_stats[i] = 0.0f;
}
__global__ void k_count(const int* __restrict__ dst, const float* __restrict__ ew) {
    int e = blockIdx.x * 256 + threadIdx.x;
    if (e < EE) {
        int d = dst[e];
        g_rank[e] = atomicAdd(&g_cnt[d], 1);
        atomicAdd(&g_deg[d], ew[e]);
    }
}
__global__ void k_scanA() {
    __shared__ int wsum[8];
    const int t = threadIdx.x;
    const int idx = blockIdx.x * 1024 + t * 4;
    int4 v = *(const int4*)&g_cnt[idx];
    int s = v.x + v.y + v.z + v.w;
    int x = s;
    #pragma unroll
    for (int o = 1; o < 32; o <<= 1) {
        int tt = __shfl_up_sync(0xffffffffu, x, o);
        if ((t & 31) >= o) x += tt;
    }
    if ((t & 31) == 31) wsum[t >> 5] = x;
    __syncthreads();
    if (t < 8) {
        int w = wsum[t];
        #pragma unroll
        for (int o = 1; o < 8; o <<= 1) {
            int tt = __shfl_up_sync(0xffu, w, o);
            if (t >= o) w += tt;
        }
        wsum[t] = w;
    }
    __syncthreads();
    int woff = (t >= 32) ? wsum[(t >> 5) - 1] : 0;
    int ex = x - s + woff;
    g_rowptr[idx + 0] = ex;
    g_rowptr[idx + 1] = ex + v.x;
    g_rowptr[idx + 2] = ex + v.x + v.y;
    g_rowptr[idx + 3] = ex + v.x + v.y + v.z;
    if (t == 0) g_blksum[blockIdx.x] = wsum[7];
    #pragma unroll
    for (int j = 0; j < 4; j++) {
        int i = idx + j;
        if (i < NN) g_dinv[i] = rsqrtf(g_deg[i]);
    }
}
__global__ void k_scanB() {
    __shared__ int sh[2];
    const int t = threadIdx.x;
    int v = (t < SCAN_BLKS) ? g_blksum[t] : 0;
    int x = v;
    #pragma unroll
    for (int o = 1; o < 32; o <<= 1) {
        int tt = __shfl_up_sync(0xffffffffu, x, o);
        if ((t & 31) >= o) x += tt;
    }
    if ((t & 31) == 31) sh[t >> 5] = x;
    __syncthreads();
    int woff = (t >= 32) ? sh[0] : 0;
    int incl = x + woff;
    if (t < SCAN_BLKS) g_blkoff[t] = incl - v;
}
__global__ void k_scanC() {
    int off = g_blkoff[blockIdx.x];
    int idx = blockIdx.x * 1024 + threadIdx.x * 4;
    int4 v = *(const int4*)&g_rowptr[idx];
    v.x += off; v.y += off; v.z += off; v.w += off;
    *(int4*)&g_rowptr[idx] = v;
}
__global__ void k_fill(const int* __restrict__ src, const int* __restrict__ dst,
                       const float* __restrict__ ew) {
    int e = blockIdx.x * 256 + threadIdx.x;
    if (e < EE) {
        int s = src[e], d = dst[e];
        int pos = g_rowptr[d] + g_rank[e];
        float c = g_dinv[s] * ew[e] * g_dinv[d];
        g_csr[pos] = make_int2(s, __float_as_int(c));
    }
}

// ---------------- W prep ----------------------------------------------------
__device__ __forceinline__ void prep_one(const float* W, int N, int t,
                                         __nv_bfloat16* hi_d, __nv_bfloat16* lo_d) {
    int k = t / N, n = t % N;
    float w = W[k * N + n];
    __nv_bfloat16 h = __float2bfloat16(w);
    __nv_bfloat16 l = __float2bfloat16(w - __bfloat162float(h));
    hi_d[n * 128 + k] = h;
    lo_d[n * 128 + k] = l;
}
__global__ void k_prepw(const float* __restrict__ W1, const float* __restrict__ W2,
                        const float* __restrict__ W3) {
    int b = blockIdx.x, tid = threadIdx.x;
    if (b < 64)        prep_one(W1, 128, b * 256 + tid,         g_wblk,         g_wblk + 16384);
    else if (b < 128)  prep_one(W2, 128, (b - 64) * 256 + tid,  g_wblk + 32768, g_wblk + 49152);
    else               prep_one(W3, 64,  (b - 128) * 256 + tid, g_wblk + 65536, g_wblk + 73728);
}

// ---------------- GEMM: mma.sync bf16 3-term, ldmatrix mainloop -------------
template <int BN>
__global__ void __launch_bounds__(256, 1)
k_gemm_mma(const float* __restrict__ Aext, int coff,
           const __nv_bfloat16* __restrict__ whi, const __nv_bfloat16* __restrict__ wlo) {
    constexpr int KP = 136;
    constexpr int NT = BN / 16;
    constexpr int NJ = NT / 2;               // x4-ldmatrix B groups
    constexpr int A_HI = 0;
    constexpr int A_LO = 128 * KP * 2;       // byte delta hi->lo (A)
    constexpr int W_HI = 2 * 128 * KP * 2;
    constexpr int B_LO = BN * KP * 2;        // byte delta hi->lo (W)
    extern __shared__ char smem[];
    const uint32_t sb = smem_u32(smem);
    const float* A = Aext ? Aext : g_agg;
    const int tid = threadIdx.x;
    const int wid = tid >> 5, lane = tid & 31;
    const int warp_m = wid & 3, warp_n = wid >> 2;
    const int row_base = blockIdx.x * 128;

    for (int i = tid; i < 128 * 32; i += 256) {
        int r = i >> 5;
        int c = (i & 31) << 2;
        int gr = row_base + r;
        float4 v = make_float4(0.f, 0.f, 0.f, 0.f);
        if (gr < NN) {
            v = *(const float4*)(A + (long)gr * 128 + c);
            if (coff >= 0) {
                float4 sc = *(const float4*)(g_stats + coff + c);
                float4 sh = *(const float4*)(g_stats + coff + 128 + c);
                v.x = fmaxf(0.f, fmaf(v.x, sc.x, sh.x));
                v.y = fmaxf(0.f, fmaf(v.y, sc.y, sh.y));
                v.z = fmaxf(0.f, fmaf(v.z, sc.z, sh.z));
                v.w = fmaxf(0.f, fmaf(v.w, sc.w, sh.w));
            }
        }
        float hx = __bfloat162float(__float2bfloat16(v.x));
        float hy = __bfloat162float(__float2bfloat16(v.y));
        float hz = __bfloat162float(__float2bfloat16(v.z));
        float hw = __bfloat162float(__float2bfloat16(v.w));
        uint32_t off = (r * KP + c) * 2;
        *(uint32_t*)(smem + A_HI + off)     = packbf2(hx, hy);
        *(uint32_t*)(smem + A_HI + off + 4) = packbf2(hz, hw);
        *(uint32_t*)(smem + A_LO + off)     = packbf2(v.x - hx, v.y - hy);
        *(uint32_t*)(smem + A_LO + off + 4) = packbf2(v.z - hz, v.w - hw);
    }
    for (int i = tid; i < BN * 16; i += 256) {
        int n = i >> 4;
        int k = (i & 15) << 3;
        uint32_t off = (n * KP + k) * 2;
        *(uint4*)(smem + W_HI + off) = ((const uint4*)whi)[i];
        *(uint4*)(smem + W_HI + B_LO + off) = ((const uint4*)wlo)[i];
    }
    __syncthreads();

    // ldmatrix lane-constant base addresses
    uint32_t a_addr[2];
    #pragma unroll
    for (int mt = 0; mt < 2; mt++)
        a_addr[mt] = sb + A_HI +
            ((warp_m * 32 + mt * 16 + (lane & 15)) * KP + ((lane >> 4) << 3)) * 2;
    uint32_t b_addr[NJ];
    #pragma unroll
    for (int j = 0; j < NJ; j++)
        b_addr[j] = sb + W_HI +
            ((warp_n * (NT * 8) + j * 16 + ((lane >> 4) << 3) + (lane & 7)) * KP +
             (((lane >> 3) & 1) << 3)) * 2;

    float acc[2][NT][4];
    #pragma unroll
    for (int mt = 0; mt < 2; mt++)
        #pragma unroll
        for (int nt = 0; nt < NT; nt++)
            #pragma unroll
            for (int j = 0; j < 4; j++) acc[mt][nt][j] = 0.f;

    #pragma unroll
    for (int ks = 0; ks < 128; ks += 16) {
        const uint32_t ko = ks * 2;
        uint32_t ah[2][4], al[2][4], bh[NT][2], bl[NT][2];
        #pragma unroll
        for (int mt = 0; mt < 2; mt++) {
            LDSM_X4(ah[mt][0], ah[mt][1], ah[mt][2], ah[mt][3], a_addr[mt] + ko);
            LDSM_X4(al[mt][0], al[mt][1], al[mt][2], al[mt][3], a_addr[mt] + A_LO + ko);
        }
        #pragma unroll
        for (int j = 0; j < NJ; j++) {
            LDSM_X4(bh[2 * j][0], bh[2 * j][1], bh[2 * j + 1][0], bh[2 * j + 1][1],
                    b_addr[j] + ko);
            LDSM_X4(bl[2 * j][0], bl[2 * j][1], bl[2 * j + 1][0], bl[2 * j + 1][1],
                    b_addr[j] + B_LO + ko);
        }
        #pragma unroll
        for (int mt = 0; mt < 2; mt++)
            #pragma unroll
            for (int nt = 0; nt < NT; nt++) {
                MMA_BF16(acc[mt][nt], ah[mt], bh[nt]);
                MMA_BF16(acc[mt][nt], ah[mt], bl[nt]);
                MMA_BF16(acc[mt][nt], al[mt], bh[nt]);
            }
    }

    const int g = lane >> 2, tg = lane & 3;
    #pragma unroll
    for (int mt = 0; mt < 2; mt++) {
        int row0 = row_base + warp_m * 32 + mt * 16 + g;
        #pragma unroll
        for (int nt = 0; nt < NT; nt++) {
            int col = warp_n * (NT * 8) + nt * 8 + 2 * tg;
            if (row0 < NN)
                *(float2*)(g_h + (long)row0 * BN + col) =
                    make_float2(acc[mt][nt][0], acc[mt][nt][1]);
            if (row0 + 8 < NN)
                *(float2*)(g_h + (long)(row0 + 8) * BN + col) =
                    make_float2(acc[mt][nt][2], acc[mt][nt][3]);
        }
    }
}

// ---------------- aggregation + fused BN stats ------------------------------
__global__ void __launch_bounds__(256)
k_agg128(const float* __restrict__ bias, float* __restrict__ outp, int statsoff) {
    __shared__ float4 s_sum[8][32];
    __shared__ float4 s_sq[8][32];
    int wlocal = threadIdx.x >> 5;
    int w = (blockIdx.x * 256 + threadIdx.x) >> 5;
    int lane = threadIdx.x & 31;
    const float4* h4 = (const float4*)g_h;
    float4 b4 = ((const float4*)bias)[lane];
    float4 sf = h4[w * 32 + lane];
    float di = g_dinv[w];
    float sc = di * di;
    float4 acc;
    acc.x = fmaf(sc, sf.x, b4.x);
    acc.y = fmaf(sc, sf.y, b4.y);
    acc.z = fmaf(sc, sf.z, b4.z);
    acc.w = fmaf(sc, sf.w, b4.w);
    int e = g_rowptr[w];
    const int end = g_rowptr[w + 1];
    for (; e + 2 <= end; e += 2) {
        int2 p0 = g_csr[e], p1 = g_csr[e + 1];
        float4 v0 = h4[p0.x * 32 + lane];
        float4 v1 = h4[p1.x * 32 + lane];
        float c0 = __int_as_float(p0.y), c1 = __int_as_float(p1.y);
        acc.x = fmaf(c0, v0.x, acc.x); acc.y = fmaf(c0, v0.y, acc.y);
        acc.z = fmaf(c0, v0.z, acc.z); acc.w = fmaf(c0, v0.w, acc.w);
        acc.x = fmaf(c1, v1.x, acc.x); acc.y = fmaf(c1, v1.y, acc.y);
        acc.z = fmaf(c1, v1.z, acc.z); acc.w = fmaf(c1, v1.w, acc.w);
    }
    if (e < end) {
        int2 p = g_csr[e];
        float4 v = h4[p.x * 32 + lane];
        float c = __int_as_float(p.y);
        acc.x = fmaf(c, v.x, acc.x); acc.y = fmaf(c, v.y, acc.y);
        acc.z = fmaf(c, v.z, acc.z); acc.w = fmaf(c, v.w, acc.w);
    }
    float4* o4 = (float4*)(outp ? outp : g_agg);
    o4[w * 32 + lane] = acc;

    if (statsoff >= 0) {
        s_sum[wlocal][lane] = acc;
        s_sq[wlocal][lane] = make_float4(acc.x * acc.x, acc.y * acc.y,
                                         acc.z * acc.z, acc.w * acc.w);
        __syncthreads();
        if (threadIdx.x < 128) {
            int c = threadIdx.x;
            int l = c >> 2, comp = c & 3;
            float s = 0.f, q = 0.f;
            #pragma unroll
            for (int ww = 0; ww < 8; ww++) {
                const float* ps = (const float*)&s_sum[ww][l];
                const float* pq = (const float*)&s_sq[ww][l];
                s += ps[comp];
                q += pq[comp];
            }
            atomicAdd(&g_stats[statsoff + c], s);
            atomicAdd(&g_stats[statsoff + 128 + c], q);
        }
    }
}

__global__ void __launch_bounds__(256)
k_agg64(const float* __restrict__ bias, float* __restrict__ outp) {
    int w = (blockIdx.x * 256 + threadIdx.x) >> 5;
    int lane = threadIdx.x & 31;
    const float2* h2 = (const float2*)g_h;
    float2 b2v = ((const float2*)bias)[lane];
    float2 sf = h2[w * 32 + lane];
    float di = g_dinv[w];
    float sc = di * di;
    float2 acc;
    acc.x = fmaf(sc, sf.x, b2v.x);
    acc.y = fmaf(sc, sf.y, b2v.y);
    int e = g_rowptr[w];
    const int end = g_rowptr[w + 1];
    for (; e + 2 <= end; e += 2) {
        int2 p0 = g_csr[e], p1 = g_csr[e + 1];
        float2 v0 = h2[p0.x * 32 + lane];
        float2 v1 = h2[p1.x * 32 + lane];
        float c0 = __int_as_float(p0.y), c1 = __int_as_float(p1.y);
        acc.x = fmaf(c0, v0.x, acc.x); acc.y = fmaf(c0, v0.y, acc.y);
        acc.x = fmaf(c1, v1.x, acc.x); acc.y = fmaf(c1, v1.y, acc.y);
    }
    if (e < end) {
        int2 p = g_csr[e];
        float2 v = h2[p.x * 32 + lane];
        float c = __int_as_float(p.y);
        acc.x = fmaf(c, v.x, acc.x); acc.y = fmaf(c, v.y, acc.y);
    }
    ((float2*)outp)[w * 32 + lane] = acc;
}

__global__ void k_bnfin(int soff, int coff, const float* __restrict__ gamma,
                        const float* __restrict__ beta) {
    int c = threadIdx.x;
    if (c < 128) {
        float mean = g_stats[soff + c] * (1.0f / NN);
        float var = g_stats[soff + 128 + c] * (1.0f / NN) - mean * mean;
        float rstd = rsqrtf(var + 1e-5f);
        float sc = rstd * gamma[c];
        g_stats[coff + c] = sc;
        g_stats[coff + 128 + c] = beta[c] - mean * sc;
    }
}

// ---------------- launch ----------------------------------------------------
extern "C" void kernel_launch(void* const* d_in, const int* in_sizes, int n_in,
                              void* d_out, int out_size) {
    const float* x   = (const float*)d_in[0];
    const int*   ei  = (const int*)d_in[1];
    const float* ew  = (const float*)d_in[2];
    const float* W1  = (const float*)d_in[3];
    const float* b1  = (const float*)d_in[4];
    const float* W2  = (const float*)d_in[5];
    const float* b2  = (const float*)d_in[6];
    const float* W3  = (const float*)d_in[7];
    const float* b3  = (const float*)d_in[8];
    const float* g1  = (const float*)d_in[9];
    const float* be1 = (const float*)d_in[10];
    const float* g2  = (const float*)d_in[11];
    const float* be2 = (const float*)d_in[12];
    const int* src = ei;
    const int* dst = ei + EE;
    float* out = (float*)d_out;

    const int agg_blocks = (NN * 32) / 256;     // 6250
    const int edge_blocks = (EE + 255) / 256;   // 3125
    const int gemm_blocks = (NN + 127) / 128;   // 391
    const int SM128 = 2 * 128 * 136 * 2 + 2 * 128 * 136 * 2;   // 139264
    const int SM64  = 2 * 128 * 136 * 2 + 2 * 64 * 136 * 2;    // 104448

    __nv_bfloat16* wblk_ptr = nullptr;
    cudaGetSymbolAddress((void**)&wblk_ptr, g_wblk);
    cudaFuncSetAttribute(k_gemm_mma<128>, cudaFuncAttributeMaxDynamicSharedMemorySize, SM128);
    cudaFuncSetAttribute(k_gemm_mma<64>,  cudaFuncAttributeMaxDynamicSharedMemorySize, SM64);

    // build + layer-1 GEMM (gemm1 reordered to launch slot 4 for ncu visibility;
    // it depends only on prepw, not on the CSR chain)
    k_prepw<<<160, 256>>>(W1, W2, W3);
    k_init<<<(NPAD + 255) / 256, 256>>>();
    k_count<<<edge_blocks, 256>>>(dst, ew);
    k_gemm_mma<128><<<gemm_blocks, 256, SM128>>>(x, -1, wblk_ptr, wblk_ptr + 16384);
    k_scanA<<<SCAN_BLKS, 256>>>();
    k_scanB<<<1, 64>>>();
    k_scanC<<<SCAN_BLKS, 256>>>();
    k_fill<<<edge_blocks, 256>>>(src, dst, ew);

    // layer 1 aggregation
    k_agg128<<<agg_blocks, 256>>>(b1, nullptr, 0);
    k_bnfin<<<1, 128>>>(0, 512, g1, be1);

    // layer 2
    k_gemm_mma<128><<<gemm_blocks, 256, SM128>>>(nullptr, 512,
        wblk_ptr + 32768, wblk_ptr + 49152);
    k_agg128<<<agg_blocks, 256>>>(b2, nullptr, 256);
    k_bnfin<<<1, 128>>>(256, 768, g2, be2);

    // layer 3 (N = 64)
    k_gemm_mma<64><<<gemm_blocks, 256, SM64>>>(nullptr, 768,
        wblk_ptr + 65536, wblk_ptr + 73728);
    k_agg64<<<agg_blocks, 256>>>(b3, out);
}

// round 15
// speedup vs baseline: 1.0977x; 1.0977x over previous
#include <cuda_runtime.h>
#include <cuda_bf16.h>
#include <cstdint>

static constexpr int NN = 50000;
static constexpr int EE = 800000;
static constexpr int SCAN_BLKS = (NN + 1023) / 1024;   // 49
static constexpr int NPAD = NN + 256;                  // >= SCAN_BLKS*1024

// ---------------- scratch (device globals; no allocation allowed) ----------
__device__ float g_h[NN * 128];
__device__ float g_agg[NN * 128];
__device__ float g_deg[NN];
__device__ float g_dinv[NN];
__device__ int   g_cnt[NPAD];
__device__ int   g_rank[EE];
__device__ int   g_rowptr[NPAD];
__device__ int2  g_csr[EE];
__device__ float g_stats[1024];
__device__ int   g_blksum[SCAN_BLKS];
__device__ int   g_blkoff[SCAN_BLKS];
__device__ __align__(16) __nv_bfloat16 g_wblk[81920];

__device__ __forceinline__ uint32_t smem_u32(const void* p) {
    uint32_t a;
    asm("{ .reg .u64 t; cvta.to.shared.u64 t, %1; cvt.u32.u64 %0, t; }" : "=r"(a) : "l"(p));
    return a;
}
__device__ __forceinline__ uint32_t packbf2(float x, float y) {
    __nv_bfloat162 p = __floats2bfloat162_rn(x, y);
    return *(uint32_t*)&p;
}

#define MMA_BF16(d, a, b) \
    asm volatile("mma.sync.aligned.m16n8k16.row.col.f32.bf16.bf16.f32 " \
        "{%0,%1,%2,%3}, {%4,%5,%6,%7}, {%8,%9}, {%0,%1,%2,%3};" \
        : "+f"((d)[0]), "+f"((d)[1]), "+f"((d)[2]), "+f"((d)[3]) \
        : "r"((a)[0]), "r"((a)[1]), "r"((a)[2]), "r"((a)[3]), "r"((b)[0]), "r"((b)[1]))
#define LDSM_X4(r0, r1, r2, r3, addr) \
    asm volatile("ldmatrix.sync.aligned.m8n8.x4.shared.b16 {%0,%1,%2,%3}, [%4];" \
        : "=r"(r0), "=r"(r1), "=r"(r2), "=r"(r3) : "r"(addr))

// ---------------- CSR build ------------------------------------------------
__global__ void k_init() {
    int i = blockIdx.x * 256 + threadIdx.x;
    if (i < NN) { g_deg[i] = 1.0f; }
    if (i < NPAD) g_cnt[i] = 0;
    if (i < 1024) g_stats[i] = 0.0f;
}
__global__ void k_count(const int* __restrict__ dst, const float* __restrict__ ew) {
    int e = blockIdx.x * 256 + threadIdx.x;
    if (e < EE) {
        int d = dst[e];
        g_rank[e] = atomicAdd(&g_cnt[d], 1);
        atomicAdd(&g_deg[d], ew[e]);
    }
}
__global__ void k_scanA() {
    __shared__ int wsum[8];
    const int t = threadIdx.x;
    const int idx = blockIdx.x * 1024 + t * 4;
    int4 v = *(const int4*)&g_cnt[idx];
    int s = v.x + v.y + v.z + v.w;
    int x = s;
    #pragma unroll
    for (int o = 1; o < 32; o <<= 1) {
        int tt = __shfl_up_sync(0xffffffffu, x, o);
        if ((t & 31) >= o) x += tt;
    }
    if ((t & 31) == 31) wsum[t >> 5] = x;
    __syncthreads();
    if (t < 8) {
        int w = wsum[t];
        #pragma unroll
        for (int o = 1; o < 8; o <<= 1) {
            int tt = __shfl_up_sync(0xffu, w, o);
            if (t >= o) w += tt;
        }
        wsum[t] = w;
    }
    __syncthreads();
    int woff = (t >= 32) ? wsum[(t >> 5) - 1] : 0;
    int ex = x - s + woff;
    g_rowptr[idx + 0] = ex;
    g_rowptr[idx + 1] = ex + v.x;
    g_rowptr[idx + 2] = ex + v.x + v.y;
    g_rowptr[idx + 3] = ex + v.x + v.y + v.z;
    if (t == 0) g_blksum[blockIdx.x] = wsum[7];
    #pragma unroll
    for (int j = 0; j < 4; j++) {
        int i = idx + j;
        if (i < NN) g_dinv[i] = rsqrtf(g_deg[i]);
    }
}
__global__ void k_scanB() {
    __shared__ int sh[2];
    const int t = threadIdx.x;
    int v = (t < SCAN_BLKS) ? g_blksum[t] : 0;
    int x = v;
    #pragma unroll
    for (int o = 1; o < 32; o <<= 1) {
        int tt = __shfl_up_sync(0xffffffffu, x, o);
        if ((t & 31) >= o) x += tt;
    }
    if ((t & 31) == 31) sh[t >> 5] = x;
    __syncthreads();
    int woff = (t >= 32) ? sh[0] : 0;
    int incl = x + woff;
    if (t < SCAN_BLKS) g_blkoff[t] = incl - v;
}
__global__ void k_scanC() {
    int off = g_blkoff[blockIdx.x];
    int idx = blockIdx.x * 1024 + threadIdx.x * 4;
    int4 v = *(const int4*)&g_rowptr[idx];
    v.x += off; v.y += off; v.z += off; v.w += off;
    *(int4*)&g_rowptr[idx] = v;
}
__global__ void k_fill(const int* __restrict__ src, const int* __restrict__ dst,
                       const float* __restrict__ ew) {
    int e = blockIdx.x * 256 + threadIdx.x;
    if (e < EE) {
        int s = src[e], d = dst[e];
        int pos = g_rowptr[d] + g_rank[e];
        float c = g_dinv[s] * ew[e] * g_dinv[d];
        g_csr[pos] = make_int2(s, __float_as_int(c));
    }
}

// ---------------- W prep ----------------------------------------------------
__device__ __forceinline__ void prep_one(const float* W, int N, int t,
                                         __nv_bfloat16* hi_d, __nv_bfloat16* lo_d) {
    int k = t / N, n = t % N;
    float w = W[k * N + n];
    __nv_bfloat16 h = __float2bfloat16(w);
    __nv_bfloat16 l = __float2bfloat16(w - __bfloat162float(h));
    hi_d[n * 128 + k] = h;
    lo_d[n * 128 + k] = l;
}
__global__ void k_prepw(const float* __restrict__ W1, const float* __restrict__ W2,
                        const float* __restrict__ W3) {
    int b = blockIdx.x, tid = threadIdx.x;
    if (b < 64)        prep_one(W1, 128, b * 256 + tid,         g_wblk,         g_wblk + 16384);
    else if (b < 128)  prep_one(W2, 128, (b - 64) * 256 + tid,  g_wblk + 32768, g_wblk + 49152);
    else               prep_one(W3, 64,  (b - 128) * 256 + tid, g_wblk + 65536, g_wblk + 73728);
}

// ---------------- GEMM: mma.sync bf16 3-term, 512 thr, 4x4 warp grid --------
template <int BN>
__global__ void __launch_bounds__(512, 1)
k_gemm_mma(const float* __restrict__ Aext, int coff,
           const __nv_bfloat16* __restrict__ whi, const __nv_bfloat16* __restrict__ wlo) {
    constexpr int KP = 136;
    constexpr int NT = BN / 32;              // n8 tiles per warp (4 or 2)
    constexpr int NJ = NT / 2;               // x4-ldmatrix B groups (2 or 1)
    constexpr int A_HI = 0;
    constexpr int A_LO = 128 * KP * 2;       // byte delta hi->lo (A)
    constexpr int W_HI = 2 * 128 * KP * 2;
    constexpr int B_LO = BN * KP * 2;        // byte delta hi->lo (W)
    extern __shared__ char smem[];
    const uint32_t sb = smem_u32(smem);
    const float* A = Aext ? Aext : g_agg;
    const int tid = threadIdx.x;
    const int wid = tid >> 5, lane = tid & 31;
    const int warp_m = wid & 3, warp_n = wid >> 2;   // 4 x 4 warps
    const int row_base = blockIdx.x * 128;

    for (int i = tid; i < 128 * 32; i += 512) {
        int r = i >> 5;
        int c = (i & 31) << 2;
        int gr = row_base + r;
        float4 v = make_float4(0.f, 0.f, 0.f, 0.f);
        if (gr < NN) {
            v = *(const float4*)(A + (long)gr * 128 + c);
            if (coff >= 0) {
                float4 sc = *(const float4*)(g_stats + coff + c);
                float4 sh = *(const float4*)(g_stats + coff + 128 + c);
                v.x = fmaxf(0.f, fmaf(v.x, sc.x, sh.x));
                v.y = fmaxf(0.f, fmaf(v.y, sc.y, sh.y));
                v.z = fmaxf(0.f, fmaf(v.z, sc.z, sh.z));
                v.w = fmaxf(0.f, fmaf(v.w, sc.w, sh.w));
            }
        }
        float hx = __bfloat162float(__float2bfloat16(v.x));
        float hy = __bfloat162float(__float2bfloat16(v.y));
        float hz = __bfloat162float(__float2bfloat16(v.z));
        float hw = __bfloat162float(__float2bfloat16(v.w));
        uint32_t off = (r * KP + c) * 2;
        *(uint32_t*)(smem + A_HI + off)     = packbf2(hx, hy);
        *(uint32_t*)(smem + A_HI + off + 4) = packbf2(hz, hw);
        *(uint32_t*)(smem + A_LO + off)     = packbf2(v.x - hx, v.y - hy);
        *(uint32_t*)(smem + A_LO + off + 4) = packbf2(v.z - hz, v.w - hw);
    }
    for (int i = tid; i < BN * 16; i += 512) {
        int n = i >> 4;
        int k = (i & 15) << 3;
        uint32_t off = (n * KP + k) * 2;
        *(uint4*)(smem + W_HI + off) = ((const uint4*)whi)[i];
        *(uint4*)(smem + W_HI + B_LO + off) = ((const uint4*)wlo)[i];
    }
    __syncthreads();

    // ldmatrix lane-constant base addresses
    uint32_t a_addr[2];
    #pragma unroll
    for (int mt = 0; mt < 2; mt++)
        a_addr[mt] = sb + A_HI +
            ((warp_m * 32 + mt * 16 + (lane & 15)) * KP + ((lane >> 4) << 3)) * 2;
    uint32_t b_addr[NJ];
    #pragma unroll
    for (int j = 0; j < NJ; j++)
        b_addr[j] = sb + W_HI +
            ((warp_n * (NT * 8) + j * 16 + ((lane >> 4) << 3) + (lane & 7)) * KP +
             (((lane >> 3) & 1) << 3)) * 2;

    float acc[2][NT][4];
    #pragma unroll
    for (int mt = 0; mt < 2; mt++)
        #pragma unroll
        for (int nt = 0; nt < NT; nt++)
            #pragma unroll
            for (int j = 0; j < 4; j++) acc[mt][nt][j] = 0.f;

    #pragma unroll
    for (int ks = 0; ks < 128; ks += 16) {
        const uint32_t ko = ks * 2;
        uint32_t ah[2][4], al[2][4], bh[NT][2], bl[NT][2];
        #pragma unroll
        for (int mt = 0; mt < 2; mt++) {
            LDSM_X4(ah[mt][0], ah[mt][1], ah[mt][2], ah[mt][3], a_addr[mt] + ko);
            LDSM_X4(al[mt][0], al[mt][1], al[mt][2], al[mt][3], a_addr[mt] + A_LO + ko);
        }
        #pragma unroll
        for (int j = 0; j < NJ; j++) {
            LDSM_X4(bh[2 * j][0], bh[2 * j][1], bh[2 * j + 1][0], bh[2 * j + 1][1],
                    b_addr[j] + ko);
            LDSM_X4(bl[2 * j][0], bl[2 * j][1], bl[2 * j + 1][0], bl[2 * j + 1][1],
                    b_addr[j] + B_LO + ko);
        }
        #pragma unroll
        for (int mt = 0; mt < 2; mt++)
            #pragma unroll
            for (int nt = 0; nt < NT; nt++) {
                MMA_BF16(acc[mt][nt], ah[mt], bh[nt]);
                MMA_BF16(acc[mt][nt], ah[mt], bl[nt]);
                MMA_BF16(acc[mt][nt], al[mt], bh[nt]);
            }
    }

    const int g = lane >> 2, tg = lane & 3;
    #pragma unroll
    for (int mt = 0; mt < 2; mt++) {
        int row0 = row_base + warp_m * 32 + mt * 16 + g;
        #pragma unroll
        for (int nt = 0; nt < NT; nt++) {
            int col = warp_n * (NT * 8) + nt * 8 + 2 * tg;
            if (row0 < NN)
                *(float2*)(g_h + (long)row0 * BN + col) =
                    make_float2(acc[mt][nt][0], acc[mt][nt][1]);
            if (row0 + 8 < NN)
                *(float2*)(g_h + (long)(row0 + 8) * BN + col) =
                    make_float2(acc[mt][nt][2], acc[mt][nt][3]);
        }
    }
}

// ---------------- aggregation + fused BN stats ------------------------------
__global__ void __launch_bounds__(256)
k_agg128(const float* __restrict__ bias, float* __restrict__ outp, int statsoff) {
    __shared__ float4 s_sum[8][32];
    __shared__ float4 s_sq[8][32];
    int wlocal = threadIdx.x >> 5;
    int w = (blockIdx.x * 256 + threadIdx.x) >> 5;
    int lane = threadIdx.x & 31;
    const float4* h4 = (const float4*)g_h;
    float4 b4 = ((const float4*)bias)[lane];
    float4 sf = h4[w * 32 + lane];
    float di = g_dinv[w];
    float sc = di * di;
    float4 acc;
    acc.x = fmaf(sc, sf.x, b4.x);
    acc.y = fmaf(sc, sf.y, b4.y);
    acc.z = fmaf(sc, sf.z, b4.z);
    acc.w = fmaf(sc, sf.w, b4.w);
    int e = g_rowptr[w];
    const int end = g_rowptr[w + 1];
    for (; e + 2 <= end; e += 2) {
        int2 p0 = g_csr[e], p1 = g_csr[e + 1];
        float4 v0 = h4[p0.x * 32 + lane];
        float4 v1 = h4[p1.x * 32 + lane];
        float c0 = __int_as_float(p0.y), c1 = __int_as_float(p1.y);
        acc.x = fmaf(c0, v0.x, acc.x); acc.y = fmaf(c0, v0.y, acc.y);
        acc.z = fmaf(c0, v0.z, acc.z); acc.w = fmaf(c0, v0.w, acc.w);
        acc.x = fmaf(c1, v1.x, acc.x); acc.y = fmaf(c1, v1.y, acc.y);
        acc.z = fmaf(c1, v1.z, acc.z); acc.w = fmaf(c1, v1.w, acc.w);
    }
    if (e < end) {
        int2 p = g_csr[e];
        float4 v = h4[p.x * 32 + lane];
        float c = __int_as_float(p.y);
        acc.x = fmaf(c, v.x, acc.x); acc.y = fmaf(c, v.y, acc.y);
        acc.z = fmaf(c, v.z, acc.z); acc.w = fmaf(c, v.w, acc.w);
    }
    float4* o4 = (float4*)(outp ? outp : g_agg);
    o4[w * 32 + lane] = acc;

    if (statsoff >= 0) {
        s_sum[wlocal][lane] = acc;
        s_sq[wlocal][lane] = make_float4(acc.x * acc.x, acc.y * acc.y,
                                         acc.z * acc.z, acc.w * acc.w);
        __syncthreads();
        if (threadIdx.x < 128) {
            int c = threadIdx.x;
            int l = c >> 2, comp = c & 3;
            float s = 0.f, q = 0.f;
            #pragma unroll
            for (int ww = 0; ww < 8; ww++) {
                const float* ps = (const float*)&s_sum[ww][l];
                const float* pq = (const float*)&s_sq[ww][l];
                s += ps[comp];
                q += pq[comp];
            }
            atomicAdd(&g_stats[statsoff + c], s);
            atomicAdd(&g_stats[statsoff + 128 + c], q);
        }
    }
}

__global__ void __launch_bounds__(256)
k_agg64(const float* __restrict__ bias, float* __restrict__ outp) {
    int w = (blockIdx.x * 256 + threadIdx.x) >> 5;
    int lane = threadIdx.x & 31;
    const float2* h2 = (const float2*)g_h;
    float2 b2v = ((const float2*)bias)[lane];
    float2 sf = h2[w * 32 + lane];
    float di = g_dinv[w];
    float sc = di * di;
    float2 acc;
    acc.x = fmaf(sc, sf.x, b2v.x);
    acc.y = fmaf(sc, sf.y, b2v.y);
    int e = g_rowptr[w];
    const int end = g_rowptr[w + 1];
    for (; e + 2 <= end; e += 2) {
        int2 p0 = g_csr[e], p1 = g_csr[e + 1];
        float2 v0 = h2[p0.x * 32 + lane];
        float2 v1 = h2[p1.x * 32 + lane];
        float c0 = __int_as_float(p0.y), c1 = __int_as_float(p1.y);
        acc.x = fmaf(c0, v0.x, acc.x); acc.y = fmaf(c0, v0.y, acc.y);
        acc.x = fmaf(c1, v1.x, acc.x); acc.y = fmaf(c1, v1.y, acc.y);
    }
    if (e < end) {
        int2 p = g_csr[e];
        float2 v = h2[p.x * 32 + lane];
        float c = __int_as_float(p.y);
        acc.x = fmaf(c, v.x, acc.x); acc.y = fmaf(c, v.y, acc.y);
    }
    ((float2*)outp)[w * 32 + lane] = acc;
}

__global__ void k_bnfin(int soff, int coff, const float* __restrict__ gamma,
                        const float* __restrict__ beta) {
    int c = threadIdx.x;
    if (c < 128) {
        float mean = g_stats[soff + c] * (1.0f / NN);
        float var = g_stats[soff + 128 + c] * (1.0f / NN) - mean * mean;
        float rstd = rsqrtf(var + 1e-5f);
        float sc = rstd * gamma[c];
        g_stats[coff + c] = sc;
        g_stats[coff + 128 + c] = beta[c] - mean * sc;
    }
}

// ---------------- launch ----------------------------------------------------
extern "C" void kernel_launch(void* const* d_in, const int* in_sizes, int n_in,
                              void* d_out, int out_size) {
    const float* x   = (const float*)d_in[0];
    const int*   ei  = (const int*)d_in[1];
    const float* ew  = (const float*)d_in[2];
    const float* W1  = (const float*)d_in[3];
    const float* b1  = (const float*)d_in[4];
    const float* W2  = (const float*)d_in[5];
    const float* b2  = (const float*)d_in[6];
    const float* W3  = (const float*)d_in[7];
    const float* b3  = (const float*)d_in[8];
    const float* g1  = (const float*)d_in[9];
    const float* be1 = (const float*)d_in[10];
    const float* g2  = (const float*)d_in[11];
    const float* be2 = (const float*)d_in[12];
    const int* src = ei;
    const int* dst = ei + EE;
    float* out = (float*)d_out;

    const int agg_blocks = (NN * 32) / 256;     // 6250
    const int edge_blocks = (EE + 255) / 256;   // 3125
    const int gemm_blocks = (NN + 127) / 128;   // 391
    const int SM128 = 2 * 128 * 136 * 2 + 2 * 128 * 136 * 2;   // 139264
    const int SM64  = 2 * 128 * 136 * 2 + 2 * 64 * 136 * 2;    // 104448

    __nv_bfloat16* wblk_ptr = nullptr;
    cudaGetSymbolAddress((void**)&wblk_ptr, g_wblk);
    cudaFuncSetAttribute(k_gemm_mma<128>, cudaFuncAttributeMaxDynamicSharedMemorySize, SM128);
    cudaFuncSetAttribute(k_gemm_mma<64>,  cudaFuncAttributeMaxDynamicSharedMemorySize, SM64);

    // build + layer-1 GEMM (gemm1 kept in ncu slot 4)
    k_prepw<<<160, 256>>>(W1, W2, W3);
    k_init<<<(NPAD + 255) / 256, 256>>>();
    k_count<<<edge_blocks, 256>>>(dst, ew);
    k_gemm_mma<128><<<gemm_blocks, 512, SM128>>>(x, -1, wblk_ptr, wblk_ptr + 16384);
    k_scanA<<<SCAN_BLKS, 256>>>();
    k_scanB<<<1, 64>>>();
    k_scanC<<<SCAN_BLKS, 256>>>();
    k_fill<<<edge_blocks, 256>>>(src, dst, ew);

    // layer 1 aggregation
    k_agg128<<<agg_blocks, 256>>>(b1, nullptr, 0);
    k_bnfin<<<1, 128>>>(0, 512, g1, be1);

    // layer 2
    k_gemm_mma<128><<<gemm_blocks, 512, SM128>>>(nullptr, 512,
        wblk_ptr + 32768, wblk_ptr + 49152);
    k_agg128<<<agg_blocks, 256>>>(b2, nullptr, 256);
    k_bnfin<<<1, 128>>>(256, 768, g2, be2);

    // layer 3 (N = 64)
    k_gemm_mma<64><<<gemm_blocks, 512, SM64>>>(nullptr, 768,
        wblk_ptr + 65536, wblk_ptr + 73728);
    k_agg64<<<agg_blocks, 256>>>(b3, out);
}

// round 16
// speedup vs baseline: 1.1062x; 1.0077x over previous
#include <cuda_runtime.h>
#include <cuda_bf16.h>
#include <cstdint>

static constexpr int NN = 50000;
static constexpr int EE = 800000;
static constexpr int SCAN_BLKS = (NN + 1023) / 1024;   // 49
static constexpr int NPAD = NN + 256;                  // >= SCAN_BLKS*1024

// ---------------- scratch (device globals; no allocation allowed) ----------
__device__ float g_h[NN * 128];
__device__ float g_agg[NN * 128];
__device__ float g_deg[NN];
__device__ float g_dinv[NN];
__device__ int   g_cnt[NPAD];
__device__ int   g_rank[EE];
__device__ int   g_rowptr[NPAD];
__device__ int2  g_csr[EE];
__device__ float g_stats[1024];
__device__ int   g_blksum[SCAN_BLKS];
__device__ int   g_blkoff[SCAN_BLKS];
__device__ __align__(16) __nv_bfloat16 g_wblk[81920];

__device__ __forceinline__ uint32_t smem_u32(const void* p) {
    uint32_t a;
    asm("{ .reg .u64 t; cvta.to.shared.u64 t, %1; cvt.u32.u64 %0, t; }" : "=r"(a) : "l"(p));
    return a;
}
__device__ __forceinline__ uint32_t packbf2(float x, float y) {
    __nv_bfloat162 p = __floats2bfloat162_rn(x, y);
    return *(uint32_t*)&p;
}

#define MMA_BF16(d, a, b) \
    asm volatile("mma.sync.aligned.m16n8k16.row.col.f32.bf16.bf16.f32 " \
        "{%0,%1,%2,%3}, {%4,%5,%6,%7}, {%8,%9}, {%0,%1,%2,%3};" \
        : "+f"((d)[0]), "+f"((d)[1]), "+f"((d)[2]), "+f"((d)[3]) \
        : "r"((a)[0]), "r"((a)[1]), "r"((a)[2]), "r"((a)[3]), "r"((b)[0]), "r"((b)[1]))
#define LDSM_X4(r0, r1, r2, r3, addr) \
    asm volatile("ldmatrix.sync.aligned.m8n8.x4.shared.b16 {%0,%1,%2,%3}, [%4];" \
        : "=r"(r0), "=r"(r1), "=r"(r2), "=r"(r3) : "r"(addr))

// fragment load / compute helpers (expand inside k_gemm_mma; names bind there)
#define LOAD_FRAGS(ko, ah, al, bh, bl) do { \
    _Pragma("unroll") \
    for (int mt = 0; mt < 2; mt++) { \
        LDSM_X4(ah[mt][0], ah[mt][1], ah[mt][2], ah[mt][3], a_addr[mt] + (ko)); \
        LDSM_X4(al[mt][0], al[mt][1], al[mt][2], al[mt][3], a_addr[mt] + A_LO + (ko)); \
    } \
    _Pragma("unroll") \
    for (int j = 0; j < NJ; j++) { \
        LDSM_X4(bh[2 * j][0], bh[2 * j][1], bh[2 * j + 1][0], bh[2 * j + 1][1], \
                b_addr[j] + (ko)); \
        LDSM_X4(bl[2 * j][0], bl[2 * j][1], bl[2 * j + 1][0], bl[2 * j + 1][1], \
                b_addr[j] + B_LO + (ko)); \
    } \
} while (0)

#define COMPUTE_FRAGS(ah, al, bh, bl) do { \
    _Pragma("unroll") \
    for (int mt = 0; mt < 2; mt++) \
        _Pragma("unroll") \
        for (int nt = 0; nt < NT; nt++) { \
            MMA_BF16(acc[mt][nt], ah[mt], bh[nt]); \
            MMA_BF16(acc[mt][nt], ah[mt], bl[nt]); \
            MMA_BF16(acc[mt][nt], al[mt], bh[nt]); \
        } \
} while (0)

// ---------------- CSR build ------------------------------------------------
__global__ void k_init() {
    int i = blockIdx.x * 256 + threadIdx.x;
    if (i < NN) { g_deg[i] = 1.0f; }
    if (i < NPAD) g_cnt[i] = 0;
    if (i < 1024) g_stats[i] = 0.0f;
}
__global__ void k_count(const int* __restrict__ dst, const float* __restrict__ ew) {
    int e = blockIdx.x * 256 + threadIdx.x;
    if (e < EE) {
        int d = dst[e];
        g_rank[e] = atomicAdd(&g_cnt[d], 1);
        atomicAdd(&g_deg[d], ew[e]);
    }
}
__global__ void k_scanA() {
    __shared__ int wsum[8];
    const int t = threadIdx.x;
    const int idx = blockIdx.x * 1024 + t * 4;
    int4 v = *(const int4*)&g_cnt[idx];
    int s = v.x + v.y + v.z + v.w;
    int x = s;
    #pragma unroll
    for (int o = 1; o < 32; o <<= 1) {
        int tt = __shfl_up_sync(0xffffffffu, x, o);
        if ((t & 31) >= o) x += tt;
    }
    if ((t & 31) == 31) wsum[t >> 5] = x;
    __syncthreads();
    if (t < 8) {
        int w = wsum[t];
        #pragma unroll
        for (int o = 1; o < 8; o <<= 1) {
            int tt = __shfl_up_sync(0xffu, w, o);
            if (t >= o) w += tt;
        }
        wsum[t] = w;
    }
    __syncthreads();
    int woff = (t >= 32) ? wsum[(t >> 5) - 1] : 0;
    int ex = x - s + woff;
    g_rowptr[idx + 0] = ex;
    g_rowptr[idx + 1] = ex + v.x;
    g_rowptr[idx + 2] = ex + v.x + v.y;
    g_rowptr[idx + 3] = ex + v.x + v.y + v.z;
    if (t == 0) g_blksum[blockIdx.x] = wsum[7];
    #pragma unroll
    for (int j = 0; j < 4; j++) {
        int i = idx + j;
        if (i < NN) g_dinv[i] = rsqrtf(g_deg[i]);
    }
}
__global__ void k_scanB() {
    __shared__ int sh[2];
    const int t = threadIdx.x;
    int v = (t < SCAN_BLKS) ? g_blksum[t] : 0;
    int x = v;
    #pragma unroll
    for (int o = 1; o < 32; o <<= 1) {
        int tt = __shfl_up_sync(0xffffffffu, x, o);
        if ((t & 31) >= o) x += tt;
    }
    if ((t & 31) == 31) sh[t >> 5] = x;
    __syncthreads();
    int woff = (t >= 32) ? sh[0] : 0;
    int incl = x + woff;
    if (t < SCAN_BLKS) g_blkoff[t] = incl - v;
}
__global__ void k_scanC() {
    int off = g_blkoff[blockIdx.x];
    int idx = blockIdx.x * 1024 + threadIdx.x * 4;
    int4 v = *(const int4*)&g_rowptr[idx];
    v.x += off; v.y += off; v.z += off; v.w += off;
    *(int4*)&g_rowptr[idx] = v;
}
__global__ void k_fill(const int* __restrict__ src, const int* __restrict__ dst,
                       const float* __restrict__ ew) {
    int e = blockIdx.x * 256 + threadIdx.x;
    if (e < EE) {
        int s = src[e], d = dst[e];
        int pos = g_rowptr[d] + g_rank[e];
        float c = g_dinv[s] * ew[e] * g_dinv[d];
        g_csr[pos] = make_int2(s, __float_as_int(c));
    }
}

// ---------------- W prep ----------------------------------------------------
__device__ __forceinline__ void prep_one(const float* W, int N, int t,
                                         __nv_bfloat16* hi_d, __nv_bfloat16* lo_d) {
    int k = t / N, n = t % N;
    float w = W[k * N + n];
    __nv_bfloat16 h = __float2bfloat16(w);
    __nv_bfloat16 l = __float2bfloat16(w - __bfloat162float(h));
    hi_d[n * 128 + k] = h;
    lo_d[n * 128 + k] = l;
}
__global__ void k_prepw(const float* __restrict__ W1, const float* __restrict__ W2,
                        const float* __restrict__ W3) {
    int b = blockIdx.x, tid = threadIdx.x;
    if (b < 64)        prep_one(W1, 128, b * 256 + tid,         g_wblk,         g_wblk + 16384);
    else if (b < 128)  prep_one(W2, 128, (b - 64) * 256 + tid,  g_wblk + 32768, g_wblk + 49152);
    else               prep_one(W3, 64,  (b - 128) * 256 + tid, g_wblk + 65536, g_wblk + 73728);
}

// ---------------- GEMM: bf16 3-term, pipelined, fused BN-finalize -----------
// soff >= 0: compute scale/shift from g_stats sums (soff) + gamma/beta, then
// apply relu(v*scale+shift) to A on load.
template <int BN>
__global__ void __launch_bounds__(512, 1)
k_gemm_mma(const float* __restrict__ Aext, int soff,
           const float* __restrict__ gamma, const float* __restrict__ beta,
           const __nv_bfloat16* __restrict__ whi, const __nv_bfloat16* __restrict__ wlo) {
    constexpr int KP = 136;
    constexpr int NT = BN / 32;              // n8 tiles per warp (4 or 2)
    constexpr int NJ = NT / 2;               // x4-ldmatrix B groups (2 or 1)
    constexpr int A_HI = 0;
    constexpr int A_LO = 128 * KP * 2;       // byte delta hi->lo (A)
    constexpr int W_HI = 2 * 128 * KP * 2;
    constexpr int B_LO = BN * KP * 2;        // byte delta hi->lo (W)
    constexpr int SS_OFF = W_HI + 2 * BN * KP * 2;   // scale[128] + shift[128]
    extern __shared__ char smem[];
    const uint32_t sb = smem_u32(smem);
    const float* A = Aext ? Aext : g_agg;
    const int tid = threadIdx.x;
    const int wid = tid >> 5, lane = tid & 31;
    const int warp_m = wid & 3, warp_n = wid >> 2;   // 4 x 4 warps
    const int row_base = blockIdx.x * 128;

    if (soff >= 0) {
        if (tid < 128) {
            float mean = g_stats[soff + tid] * (1.0f / NN);
            float var = g_stats[soff + 128 + tid] * (1.0f / NN) - mean * mean;
            float rstd = rsqrtf(var + 1e-5f);
            float scv = rstd * gamma[tid];
            *(float*)(smem + SS_OFF + tid * 4)       = scv;
            *(float*)(smem + SS_OFF + 512 + tid * 4) = beta[tid] - mean * scv;
        }
        __syncthreads();
    }

    for (int i = tid; i < 128 * 32; i += 512) {
        int r = i >> 5;
        int c = (i & 31) << 2;
        int gr = row_base + r;
        float4 v = make_float4(0.f, 0.f, 0.f, 0.f);
        if (gr < NN) {
            v = *(const float4*)(A + (long)gr * 128 + c);
            if (soff >= 0) {
                float4 sc = *(const float4*)(smem + SS_OFF + c * 4);
                float4 sh = *(const float4*)(smem + SS_OFF + 512 + c * 4);
                v.x = fmaxf(0.f, fmaf(v.x, sc.x, sh.x));
                v.y = fmaxf(0.f, fmaf(v.y, sc.y, sh.y));
                v.z = fmaxf(0.f, fmaf(v.z, sc.z, sh.z));
                v.w = fmaxf(0.f, fmaf(v.w, sc.w, sh.w));
            }
        }
        float hx = __bfloat162float(__float2bfloat16(v.x));
        float hy = __bfloat162float(__float2bfloat16(v.y));
        float hz = __bfloat162float(__float2bfloat16(v.z));
        float hw = __bfloat162float(__float2bfloat16(v.w));
        uint32_t off = (r * KP + c) * 2;
        *(uint32_t*)(smem + A_HI + off)     = packbf2(hx, hy);
        *(uint32_t*)(smem + A_HI + off + 4) = packbf2(hz, hw);
        *(uint32_t*)(smem + A_LO + off)     = packbf2(v.x - hx, v.y - hy);
        *(uint32_t*)(smem + A_LO + off + 4) = packbf2(v.z - hz, v.w - hw);
    }
    for (int i = tid; i < BN * 16; i += 512) {
        int n = i >> 4;
        int k = (i & 15) << 3;
        uint32_t off = (n * KP + k) * 2;
        *(uint4*)(smem + W_HI + off) = ((const uint4*)whi)[i];
        *(uint4*)(smem + W_HI + B_LO + off) = ((const uint4*)wlo)[i];
    }
    __syncthreads();

    uint32_t a_addr[2];
    #pragma unroll
    for (int mt = 0; mt < 2; mt++)
        a_addr[mt] = sb + A_HI +
            ((warp_m * 32 + mt * 16 + (lane & 15)) * KP + ((lane >> 4) << 3)) * 2;
    uint32_t b_addr[NJ];
    #pragma unroll
    for (int j = 0; j < NJ; j++)
        b_addr[j] = sb + W_HI +
            ((warp_n * (NT * 8) + j * 16 + ((lane >> 4) << 3) + (lane & 7)) * KP +
             (((lane >> 3) & 1) << 3)) * 2;

    float acc[2][NT][4];
    #pragma unroll
    for (int mt = 0; mt < 2; mt++)
        #pragma unroll
        for (int nt = 0; nt < NT; nt++)
            #pragma unroll
            for (int j = 0; j < 4; j++) acc[mt][nt][j] = 0.f;

    // software-pipelined mainloop: double-buffered fragments
    uint32_t ah0[2][4], al0[2][4], bh0[NT][2], bl0[NT][2];
    uint32_t ah1[2][4], al1[2][4], bh1[NT][2], bl1[NT][2];
    LOAD_FRAGS(0u, ah0, al0, bh0, bl0);
    #pragma unroll
    for (int s = 0; s < 8; s++) {
        const uint32_t kon = (uint32_t)(s + 1) * 32u;   // byte offset of next k-step
        if ((s & 1) == 0) {
            if (s < 7) LOAD_FRAGS(kon, ah1, al1, bh1, bl1);
            COMPUTE_FRAGS(ah0, al0, bh0, bl0);
        } else {
            if (s < 7) LOAD_FRAGS(kon, ah0, al0, bh0, bl0);
            COMPUTE_FRAGS(ah1, al1, bh1, bl1);
        }
    }

    const int g = lane >> 2, tg = lane & 3;
    #pragma unroll
    for (int mt = 0; mt < 2; mt++) {
        int row0 = row_base + warp_m * 32 + mt * 16 + g;
        #pragma unroll
        for (int nt = 0; nt < NT; nt++) {
            int col = warp_n * (NT * 8) + nt * 8 + 2 * tg;
            if (row0 < NN)
                *(float2*)(g_h + (long)row0 * BN + col) =
                    make_float2(acc[mt][nt][0], acc[mt][nt][1]);
            if (row0 + 8 < NN)
                *(float2*)(g_h + (long)(row0 + 8) * BN + col) =
                    make_float2(acc[mt][nt][2], acc[mt][nt][3]);
        }
    }
}

// ---------------- aggregation + fused BN stats ------------------------------
__global__ void __launch_bounds__(256)
k_agg128(const float* __restrict__ bias, float* __restrict__ outp, int statsoff) {
    __shared__ float4 s_sum[8][32];
    __shared__ float4 s_sq[8][32];
    int wlocal = threadIdx.x >> 5;
    int w = (blockIdx.x * 256 + threadIdx.x) >> 5;
    int lane = threadIdx.x & 31;
    const float4* h4 = (const float4*)g_h;
    float4 b4 = ((const float4*)bias)[lane];
    float4 sf = h4[w * 32 + lane];
    float di = g_dinv[w];
    float sc = di * di;
    float4 acc;
    acc.x = fmaf(sc, sf.x, b4.x);
    acc.y = fmaf(sc, sf.y, b4.y);
    acc.z = fmaf(sc, sf.z, b4.z);
    acc.w = fmaf(sc, sf.w, b4.w);
    int e = g_rowptr[w];
    const int end = g_rowptr[w + 1];
    for (; e + 2 <= end; e += 2) {
        int2 p0 = g_csr[e], p1 = g_csr[e + 1];
        float4 v0 = h4[p0.x * 32 + lane];
        float4 v1 = h4[p1.x * 32 + lane];
        float c0 = __int_as_float(p0.y), c1 = __int_as_float(p1.y);
        acc.x = fmaf(c0, v0.x, acc.x); acc.y = fmaf(c0, v0.y, acc.y);
        acc.z = fmaf(c0, v0.z, acc.z); acc.w = fmaf(c0, v0.w, acc.w);
        acc.x = fmaf(c1, v1.x, acc.x); acc.y = fmaf(c1, v1.y, acc.y);
        acc.z = fmaf(c1, v1.z, acc.z); acc.w = fmaf(c1, v1.w, acc.w);
    }
    if (e < end) {
        int2 p = g_csr[e];
        float4 v = h4[p.x * 32 + lane];
        float c = __int_as_float(p.y);
        acc.x = fmaf(c, v.x, acc.x); acc.y = fmaf(c, v.y, acc.y);
        acc.z = fmaf(c, v.z, acc.z); acc.w = fmaf(c, v.w, acc.w);
    }
    float4* o4 = (float4*)(outp ? outp : g_agg);
    o4[w * 32 + lane] = acc;

    if (statsoff >= 0) {
        s_sum[wlocal][lane] = acc;
        s_sq[wlocal][lane] = make_float4(acc.x * acc.x, acc.y * acc.y,
                                         acc.z * acc.z, acc.w * acc.w);
        __syncthreads();
        if (threadIdx.x < 128) {
            int c = threadIdx.x;
            int l = c >> 2, comp = c & 3;
            float s = 0.f, q = 0.f;
            #pragma unroll
            for (int ww = 0; ww < 8; ww++) {
                const float* ps = (const float*)&s_sum[ww][l];
                const float* pq = (const float*)&s_sq[ww][l];
                s += ps[comp];
                q += pq[comp];
            }
            atomicAdd(&g_stats[statsoff + c], s);
            atomicAdd(&g_stats[statsoff + 128 + c], q);
        }
    }
}

__global__ void __launch_bounds__(256)
k_agg64(const float* __restrict__ bias, float* __restrict__ outp) {
    int w = (blockIdx.x * 256 + threadIdx.x) >> 5;
    int lane = threadIdx.x & 31;
    const float2* h2 = (const float2*)g_h;
    float2 b2v = ((const float2*)bias)[lane];
    float2 sf = h2[w * 32 + lane];
    float di = g_dinv[w];
    float sc = di * di;
    float2 acc;
    acc.x = fmaf(sc, sf.x, b2v.x);
    acc.y = fmaf(sc, sf.y, b2v.y);
    int e = g_rowptr[w];
    const int end = g_rowptr[w + 1];
    for (; e + 2 <= end; e += 2) {
        int2 p0 = g_csr[e], p1 = g_csr[e + 1];
        float2 v0 = h2[p0.x * 32 + lane];
        float2 v1 = h2[p1.x * 32 + lane];
        float c0 = __int_as_float(p0.y), c1 = __int_as_float(p1.y);
        acc.x = fmaf(c0, v0.x, acc.x); acc.y = fmaf(c0, v0.y, acc.y);
        acc.x = fmaf(c1, v1.x, acc.x); acc.y = fmaf(c1, v1.y, acc.y);
    }
    if (e < end) {
        int2 p = g_csr[e];
        float2 v = h2[p.x * 32 + lane];
        float c = __int_as_float(p.y);
        acc.x = fmaf(c, v.x, acc.x); acc.y = fmaf(c, v.y, acc.y);
    }
    ((float2*)outp)[w * 32 + lane] = acc;
}

// ---------------- launch ----------------------------------------------------
extern "C" void kernel_launch(void* const* d_in, const int* in_sizes, int n_in,
                              void* d_out, int out_size) {
    const float* x   = (const float*)d_in[0];
    const int*   ei  = (const int*)d_in[1];
    const float* ew  = (const float*)d_in[2];
    const float* W1  = (const float*)d_in[3];
    const float* b1  = (const float*)d_in[4];
    const float* W2  = (const float*)d_in[5];
    const float* b2  = (const float*)d_in[6];
    const float* W3  = (const float*)d_in[7];
    const float* b3  = (const float*)d_in[8];
    const float* g1  = (const float*)d_in[9];
    const float* be1 = (const float*)d_in[10];
    const float* g2  = (const float*)d_in[11];
    const float* be2 = (const float*)d_in[12];
    const int* src = ei;
    const int* dst = ei + EE;
    float* out = (float*)d_out;

    const int agg_blocks = (NN * 32) / 256;     // 6250
    const int edge_blocks = (EE + 255) / 256;   // 3125
    const int gemm_blocks = (NN + 127) / 128;   // 391
    const int SM128 = 2 * 128 * 136 * 2 + 2 * 128 * 136 * 2 + 1024;   // 140288
    const int SM64  = 2 * 128 * 136 * 2 + 2 * 64 * 136 * 2 + 1024;    // 105472

    __nv_bfloat16* wblk_ptr = nullptr;
    cudaGetSymbolAddress((void**)&wblk_ptr, g_wblk);
    cudaFuncSetAttribute(k_gemm_mma<128>, cudaFuncAttributeMaxDynamicSharedMemorySize, SM128);
    cudaFuncSetAttribute(k_gemm_mma<64>,  cudaFuncAttributeMaxDynamicSharedMemorySize, SM64);

    // build + layer-1 GEMM (gemm1 kept in ncu slot 4)
    k_prepw<<<160, 256>>>(W1, W2, W3);
    k_init<<<(NPAD + 255) / 256, 256>>>();
    k_count<<<edge_blocks, 256>>>(dst, ew);
    k_gemm_mma<128><<<gemm_blocks, 512, SM128>>>(x, -1, nullptr, nullptr,
        wblk_ptr, wblk_ptr + 16384);
    k_scanA<<<SCAN_BLKS, 256>>>();
    k_scanB<<<1, 64>>>();
    k_scanC<<<SCAN_BLKS, 256>>>();
    k_fill<<<edge_blocks, 256>>>(src, dst, ew);

    // layer 1 aggregation (+ BN stats for layer 1)
    k_agg128<<<agg_blocks, 256>>>(b1, nullptr, 0);

    // layer 2 (BN finalize of layer-1 stats fused into GEMM prologue)
    k_gemm_mma<128><<<gemm_blocks, 512, SM128>>>(nullptr, 0, g1, be1,
        wblk_ptr + 32768, wblk_ptr + 49152);
    k_agg128<<<agg_blocks, 256>>>(b2, nullptr, 256);

    // layer 3 (N = 64; BN finalize of layer-2 stats fused)
    k_gemm_mma<64><<<gemm_blocks, 512, SM64>>>(nullptr, 256, g2, be2,
        wblk_ptr + 65536, wblk_ptr + 73728);
    k_agg64<<<agg_blocks, 256>>>(b3, out);
}

// round 17
// speedup vs baseline: 1.1589x; 1.0476x over previous
#include <cuda_runtime.h>
#include <cuda_bf16.h>
#include <cstdint>

static constexpr int NN = 50000;
static constexpr int EE = 800000;
static constexpr int SCAN_BLKS = (NN + 1023) / 1024;   // 49
static constexpr int NPAD = NN + 256;                  // >= SCAN_BLKS*1024

// ---------------- scratch (device globals; no allocation allowed) ----------
__device__ float g_h[NN * 128];
__device__ float g_agg[NN * 128];
__device__ float g_deg[NN];
__device__ float g_dinv[NN];
__device__ int   g_cnt[NPAD];
__device__ int   g_rank[EE];
__device__ int   g_rowptr[NPAD];
__device__ int2  g_csr[EE];
__device__ float g_stats[1024];
__device__ int   g_blksum[SCAN_BLKS];
__device__ int   g_blkoff[SCAN_BLKS];
__device__ __align__(16) __nv_bfloat16 g_wblk[81920];

__device__ __forceinline__ uint32_t smem_u32(const void* p) {
    uint32_t a;
    asm("{ .reg .u64 t; cvta.to.shared.u64 t, %1; cvt.u32.u64 %0, t; }" : "=r"(a) : "l"(p));
    return a;
}
__device__ __forceinline__ uint32_t packbf2(float x, float y) {
    __nv_bfloat162 p = __floats2bfloat162_rn(x, y);
    return *(uint32_t*)&p;
}

#define MMA_BF16(d, a, b) \
    asm volatile("mma.sync.aligned.m16n8k16.row.col.f32.bf16.bf16.f32 " \
        "{%0,%1,%2,%3}, {%4,%5,%6,%7}, {%8,%9}, {%0,%1,%2,%3};" \
        : "+f"((d)[0]), "+f"((d)[1]), "+f"((d)[2]), "+f"((d)[3]) \
        : "r"((a)[0]), "r"((a)[1]), "r"((a)[2]), "r"((a)[3]), "r"((b)[0]), "r"((b)[1]))
#define LDSM_X4(r0, r1, r2, r3, addr) \
    asm volatile("ldmatrix.sync.aligned.m8n8.x4.shared.b16 {%0,%1,%2,%3}, [%4];" \
        : "=r"(r0), "=r"(r1), "=r"(r2), "=r"(r3) : "r"(addr))

// ---------------- CSR build ------------------------------------------------
__global__ void k_init() {
    int i = blockIdx.x * 256 + threadIdx.x;
    if (i < NN) { g_deg[i] = 1.0f; }
    if (i < NPAD) g_cnt[i] = 0;
    if (i < 1024) g_stats[i] = 0.0f;
}
__global__ void k_count(const int* __restrict__ dst, const float* __restrict__ ew) {
    int e = blockIdx.x * 256 + threadIdx.x;
    if (e < EE) {
        int d = dst[e];
        g_rank[e] = atomicAdd(&g_cnt[d], 1);
        atomicAdd(&g_deg[d], ew[e]);
    }
}
__global__ void k_scanA() {
    __shared__ int wsum[8];
    const int t = threadIdx.x;
    const int idx = blockIdx.x * 1024 + t * 4;
    int4 v = *(const int4*)&g_cnt[idx];
    int s = v.x + v.y + v.z + v.w;
    int x = s;
    #pragma unroll
    for (int o = 1; o < 32; o <<= 1) {
        int tt = __shfl_up_sync(0xffffffffu, x, o);
        if ((t & 31) >= o) x += tt;
    }
    if ((t & 31) == 31) wsum[t >> 5] = x;
    __syncthreads();
    if (t < 8) {
        int w = wsum[t];
        #pragma unroll
        for (int o = 1; o < 8; o <<= 1) {
            int tt = __shfl_up_sync(0xffu, w, o);
            if (t >= o) w += tt;
        }
        wsum[t] = w;
    }
    __syncthreads();
    int woff = (t >= 32) ? wsum[(t >> 5) - 1] : 0;
    int ex = x - s + woff;
    g_rowptr[idx + 0] = ex;
    g_rowptr[idx + 1] = ex + v.x;
    g_rowptr[idx + 2] = ex + v.x + v.y;
    g_rowptr[idx + 3] = ex + v.x + v.y + v.z;
    if (t == 0) g_blksum[blockIdx.x] = wsum[7];
    #pragma unroll
    for (int j = 0; j < 4; j++) {
        int i = idx + j;
        if (i < NN) g_dinv[i] = rsqrtf(g_deg[i]);
    }
}
__global__ void k_scanB() {
    __shared__ int sh[2];
    const int t = threadIdx.x;
    int v = (t < SCAN_BLKS) ? g_blksum[t] : 0;
    int x = v;
    #pragma unroll
    for (int o = 1; o < 32; o <<= 1) {
        int tt = __shfl_up_sync(0xffffffffu, x, o);
        if ((t & 31) >= o) x += tt;
    }
    if ((t & 31) == 31) sh[t >> 5] = x;
    __syncthreads();
    int woff = (t >= 32) ? sh[0] : 0;
    int incl = x + woff;
    if (t < SCAN_BLKS) g_blkoff[t] = incl - v;
}
__global__ void k_scanC() {
    int off = g_blkoff[blockIdx.x];
    int idx = blockIdx.x * 1024 + threadIdx.x * 4;
    int4 v = *(const int4*)&g_rowptr[idx];
    v.x += off; v.y += off; v.z += off; v.w += off;
    *(int4*)&g_rowptr[idx] = v;
}
__global__ void k_fill(const int* __restrict__ src, const int* __restrict__ dst,
                       const float* __restrict__ ew) {
    int e = blockIdx.x * 256 + threadIdx.x;
    if (e < EE) {
        int s = src[e], d = dst[e];
        int pos = g_rowptr[d] + g_rank[e];
        float c = g_dinv[s] * ew[e] * g_dinv[d];
        g_csr[pos] = make_int2(s, __float_as_int(c));
    }
}

// ---------------- W prep ----------------------------------------------------
__device__ __forceinline__ void prep_one(const float* W, int N, int t,
                                         __nv_bfloat16* hi_d, __nv_bfloat16* lo_d) {
    int k = t / N, n = t % N;
    float w = W[k * N + n];
    __nv_bfloat16 h = __float2bfloat16(w);
    __nv_bfloat16 l = __float2bfloat16(w - __bfloat162float(h));
    hi_d[n * 128 + k] = h;
    lo_d[n * 128 + k] = l;
}
__global__ void k_prepw(const float* __restrict__ W1, const float* __restrict__ W2,
                        const float* __restrict__ W3) {
    int b = blockIdx.x, tid = threadIdx.x;
    if (b < 64)        prep_one(W1, 128, b * 256 + tid,         g_wblk,         g_wblk + 16384);
    else if (b < 128)  prep_one(W2, 128, (b - 64) * 256 + tid,  g_wblk + 32768, g_wblk + 49152);
    else               prep_one(W3, 64,  (b - 128) * 256 + tid, g_wblk + 65536, g_wblk + 73728);
}

// ---------------- GEMM: bf16 3-term, M-tile 64, 2 CTAs/SM -------------------
// soff >= 0: BN-finalize fused (scale/shift from g_stats + gamma/beta).
template <int BN>
__global__ void __launch_bounds__(512, 2)
k_gemm_mma(const float* __restrict__ Aext, int soff,
           const float* __restrict__ gamma, const float* __restrict__ beta,
           const __nv_bfloat16* __restrict__ whi, const __nv_bfloat16* __restrict__ wlo) {
    constexpr int KP = 136;
    constexpr int NT = BN / 32;              // n8 tiles per warp (4 or 2)
    constexpr int NJ = NT / 2;               // x4-ldmatrix B groups (2 or 1)
    constexpr int A_HI = 0;
    constexpr int A_LO = 64 * KP * 2;        // 17408: byte delta hi->lo (A)
    constexpr int W_HI = 2 * 64 * KP * 2;    // 34816
    constexpr int B_LO = BN * KP * 2;        // byte delta hi->lo (W)
    constexpr int SS_OFF = W_HI + 2 * BN * KP * 2;   // scale[128] + shift[128]
    extern __shared__ char smem[];
    const uint32_t sb = smem_u32(smem);
    const float* A = Aext ? Aext : g_agg;
    const int tid = threadIdx.x;
    const int wid = tid >> 5, lane = tid & 31;
    const int warp_m = wid & 3, warp_n = wid >> 2;   // 4 x 4 warps over 64 x BN
    const int row_base = blockIdx.x * 64;

    if (soff >= 0) {
        if (tid < 128) {
            float mean = g_stats[soff + tid] * (1.0f / NN);
            float var = g_stats[soff + 128 + tid] * (1.0f / NN) - mean * mean;
            float rstd = rsqrtf(var + 1e-5f);
            float scv = rstd * gamma[tid];
            *(float*)(smem + SS_OFF + tid * 4)       = scv;
            *(float*)(smem + SS_OFF + 512 + tid * 4) = beta[tid] - mean * scv;
        }
        __syncthreads();
    }

    // stage A (64 rows x 128 cols, fp32 -> bf16 hi/lo, fused BN+ReLU)
    #pragma unroll
    for (int i = tid; i < 64 * 32; i += 512) {
        int r = i >> 5;
        int c = (i & 31) << 2;
        int gr = row_base + r;
        float4 v = make_float4(0.f, 0.f, 0.f, 0.f);
        if (gr < NN) {
            v = *(const float4*)(A + (long)gr * 128 + c);
            if (soff >= 0) {
                float4 sc = *(const float4*)(smem + SS_OFF + c * 4);
                float4 sh = *(const float4*)(smem + SS_OFF + 512 + c * 4);
                v.x = fmaxf(0.f, fmaf(v.x, sc.x, sh.x));
                v.y = fmaxf(0.f, fmaf(v.y, sc.y, sh.y));
                v.z = fmaxf(0.f, fmaf(v.z, sc.z, sh.z));
                v.w = fmaxf(0.f, fmaf(v.w, sc.w, sh.w));
            }
        }
        float hx = __bfloat162float(__float2bfloat16(v.x));
        float hy = __bfloat162float(__float2bfloat16(v.y));
        float hz = __bfloat162float(__float2bfloat16(v.z));
        float hw = __bfloat162float(__float2bfloat16(v.w));
        uint32_t off = (r * KP + c) * 2;
        *(uint32_t*)(smem + A_HI + off)     = packbf2(hx, hy);
        *(uint32_t*)(smem + A_HI + off + 4) = packbf2(hz, hw);
        *(uint32_t*)(smem + A_LO + off)     = packbf2(v.x - hx, v.y - hy);
        *(uint32_t*)(smem + A_LO + off + 4) = packbf2(v.z - hz, v.w - hw);
    }
    // stage W (pre-transposed hi/lo)
    #pragma unroll
    for (int i = tid; i < BN * 16; i += 512) {
        int n = i >> 4;
        int k = (i & 15) << 3;
        uint32_t off = (n * KP + k) * 2;
        *(uint4*)(smem + W_HI + off) = ((const uint4*)whi)[i];
        *(uint4*)(smem + W_HI + B_LO + off) = ((const uint4*)wlo)[i];
    }
    __syncthreads();

    const uint32_t a_addr = sb + A_HI +
        ((warp_m * 16 + (lane & 15)) * KP + ((lane >> 4) << 3)) * 2;
    uint32_t b_addr[NJ];
    #pragma unroll
    for (int j = 0; j < NJ; j++)
        b_addr[j] = sb + W_HI +
            ((warp_n * (NT * 8) + j * 16 + ((lane >> 4) << 3) + (lane & 7)) * KP +
             (((lane >> 3) & 1) << 3)) * 2;

    float acc[NT][4];
    #pragma unroll
    for (int nt = 0; nt < NT; nt++)
        #pragma unroll
        for (int j = 0; j < 4; j++) acc[nt][j] = 0.f;

    #pragma unroll
    for (int ks = 0; ks < 128; ks += 16) {
        const uint32_t ko = ks * 2;
        uint32_t ah[4], al[4], bh[NT][2], bl[NT][2];
        LDSM_X4(ah[0], ah[1], ah[2], ah[3], a_addr + ko);
        LDSM_X4(al[0], al[1], al[2], al[3], a_addr + A_LO + ko);
        #pragma unroll
        for (int j = 0; j < NJ; j++) {
            LDSM_X4(bh[2 * j][0], bh[2 * j][1], bh[2 * j + 1][0], bh[2 * j + 1][1],
                    b_addr[j] + ko);
            LDSM_X4(bl[2 * j][0], bl[2 * j][1], bl[2 * j + 1][0], bl[2 * j + 1][1],
                    b_addr[j] + B_LO + ko);
        }
        #pragma unroll
        for (int nt = 0; nt < NT; nt++) {
            MMA_BF16(acc[nt], ah, bh[nt]);
            MMA_BF16(acc[nt], ah, bl[nt]);
            MMA_BF16(acc[nt], al, bh[nt]);
        }
    }

    const int g = lane >> 2, tg = lane & 3;
    int row0 = row_base + warp_m * 16 + g;
    #pragma unroll
    for (int nt = 0; nt < NT; nt++) {
        int col = warp_n * (NT * 8) + nt * 8 + 2 * tg;
        if (row0 < NN)
            *(float2*)(g_h + (long)row0 * BN + col) =
                make_float2(acc[nt][0], acc[nt][1]);
        if (row0 + 8 < NN)
            *(float2*)(g_h + (long)(row0 + 8) * BN + col) =
                make_float2(acc[nt][2], acc[nt][3]);
    }
}

// ---------------- aggregation + fused BN stats ------------------------------
__global__ void __launch_bounds__(256)
k_agg128(const float* __restrict__ bias, float* __restrict__ outp, int statsoff) {
    __shared__ float4 s_sum[8][32];
    __shared__ float4 s_sq[8][32];
    int wlocal = threadIdx.x >> 5;
    int w = (blockIdx.x * 256 + threadIdx.x) >> 5;
    int lane = threadIdx.x & 31;
    const float4* h4 = (const float4*)g_h;
    float4 b4 = ((const float4*)bias)[lane];
    float4 sf = h4[w * 32 + lane];
    float di = g_dinv[w];
    float sc = di * di;
    float4 acc;
    acc.x = fmaf(sc, sf.x, b4.x);
    acc.y = fmaf(sc, sf.y, b4.y);
    acc.z = fmaf(sc, sf.z, b4.z);
    acc.w = fmaf(sc, sf.w, b4.w);
    int e = g_rowptr[w];
    const int end = g_rowptr[w + 1];
    for (; e + 2 <= end; e += 2) {
        int2 p0 = g_csr[e], p1 = g_csr[e + 1];
        float4 v0 = h4[p0.x * 32 + lane];
        float4 v1 = h4[p1.x * 32 + lane];
        float c0 = __int_as_float(p0.y), c1 = __int_as_float(p1.y);
        acc.x = fmaf(c0, v0.x, acc.x); acc.y = fmaf(c0, v0.y, acc.y);
        acc.z = fmaf(c0, v0.z, acc.z); acc.w = fmaf(c0, v0.w, acc.w);
        acc.x = fmaf(c1, v1.x, acc.x); acc.y = fmaf(c1, v1.y, acc.y);
        acc.z = fmaf(c1, v1.z, acc.z); acc.w = fmaf(c1, v1.w, acc.w);
    }
    if (e < end) {
        int2 p = g_csr[e];
        float4 v = h4[p.x * 32 + lane];
        float c = __int_as_float(p.y);
        acc.x = fmaf(c, v.x, acc.x); acc.y = fmaf(c, v.y, acc.y);
        acc.z = fmaf(c, v.z, acc.z); acc.w = fmaf(c, v.w, acc.w);
    }
    float4* o4 = (float4*)(outp ? outp : g_agg);
    o4[w * 32 + lane] = acc;

    if (statsoff >= 0) {
        s_sum[wlocal][lane] = acc;
        s_sq[wlocal][lane] = make_float4(acc.x * acc.x, acc.y * acc.y,
                                         acc.z * acc.z, acc.w * acc.w);
        __syncthreads();
        if (threadIdx.x < 128) {
            int c = threadIdx.x;
            int l = c >> 2, comp = c & 3;
            float s = 0.f, q = 0.f;
            #pragma unroll
            for (int ww = 0; ww < 8; ww++) {
                const float* ps = (const float*)&s_sum[ww][l];
                const float* pq = (const float*)&s_sq[ww][l];
                s += ps[comp];
                q += pq[comp];
            }
            atomicAdd(&g_stats[statsoff + c], s);
            atomicAdd(&g_stats[statsoff + 128 + c], q);
        }
    }
}

__global__ void __launch_bounds__(256)
k_agg64(const float* __restrict__ bias, float* __restrict__ outp) {
    int w = (blockIdx.x * 256 + threadIdx.x) >> 5;
    int lane = threadIdx.x & 31;
    const float2* h2 = (const float2*)g_h;
    float2 b2v = ((const float2*)bias)[lane];
    float2 sf = h2[w * 32 + lane];
    float di = g_dinv[w];
    float sc = di * di;
    float2 acc;
    acc.x = fmaf(sc, sf.x, b2v.x);
    acc.y = fmaf(sc, sf.y, b2v.y);
    int e = g_rowptr[w];
    const int end = g_rowptr[w + 1];
    for (; e + 2 <= end; e += 2) {
        int2 p0 = g_csr[e], p1 = g_csr[e + 1];
        float2 v0 = h2[p0.x * 32 + lane];
        float2 v1 = h2[p1.x * 32 + lane];
        float c0 = __int_as_float(p0.y), c1 = __int_as_float(p1.y);
        acc.x = fmaf(c0, v0.x, acc.x); acc.y = fmaf(c0, v0.y, acc.y);
        acc.x = fmaf(c1, v1.x, acc.x); acc.y = fmaf(c1, v1.y, acc.y);
    }
    if (e < end) {
        int2 p = g_csr[e];
        float2 v = h2[p.x * 32 + lane];
        float c = __int_as_float(p.y);
        acc.x = fmaf(c, v.x, acc.x); acc.y = fmaf(c, v.y, acc.y);
    }
    ((float2*)outp)[w * 32 + lane] = acc;
}

// ---------------- launch ----------------------------------------------------
extern "C" void kernel_launch(void* const* d_in, const int* in_sizes, int n_in,
                              void* d_out, int out_size) {
    const float* x   = (const float*)d_in[0];
    const int*   ei  = (const int*)d_in[1];
    const float* ew  = (const float*)d_in[2];
    const float* W1  = (const float*)d_in[3];
    const float* b1  = (const float*)d_in[4];
    const float* W2  = (const float*)d_in[5];
    const float* b2  = (const float*)d_in[6];
    const float* W3  = (const float*)d_in[7];
    const float* b3  = (const float*)d_in[8];
    const float* g1  = (const float*)d_in[9];
    const float* be1 = (const float*)d_in[10];
    const float* g2  = (const float*)d_in[11];
    const float* be2 = (const float*)d_in[12];
    const int* src = ei;
    const int* dst = ei + EE;
    float* out = (float*)d_out;

    const int agg_blocks = (NN * 32) / 256;     // 6250
    const int edge_blocks = (EE + 255) / 256;   // 3125
    const int gemm_blocks = (NN + 63) / 64;     // 782
    const int SM128 = 2 * 64 * 136 * 2 + 2 * 128 * 136 * 2 + 1024;   // 105472
    const int SM64  = 2 * 64 * 136 * 2 + 2 * 64 * 136 * 2 + 1024;    // 70656

    __nv_bfloat16* wblk_ptr = nullptr;
    cudaGetSymbolAddress((void**)&wblk_ptr, g_wblk);
    cudaFuncSetAttribute(k_gemm_mma<128>, cudaFuncAttributeMaxDynamicSharedMemorySize, SM128);
    cudaFuncSetAttribute(k_gemm_mma<64>,  cudaFuncAttributeMaxDynamicSharedMemorySize, SM64);

    // build + layer-1 GEMM (gemm1 kept in ncu slot 4)
    k_prepw<<<160, 256>>>(W1, W2, W3);
    k_init<<<(NPAD + 255) / 256, 256>>>();
    k_count<<<edge_blocks, 256>>>(dst, ew);
    k_gemm_mma<128><<<gemm_blocks, 512, SM128>>>(x, -1, nullptr, nullptr,
        wblk_ptr, wblk_ptr + 16384);
    k_scanA<<<SCAN_BLKS, 256>>>();
    k_scanB<<<1, 64>>>();
    k_scanC<<<SCAN_BLKS, 256>>>();
    k_fill<<<edge_blocks, 256>>>(src, dst, ew);

    // layer 1 aggregation (+ BN stats for layer 1)
    k_agg128<<<agg_blocks, 256>>>(b1, nullptr, 0);

    // layer 2 (BN finalize of layer-1 stats fused into GEMM prologue)
    k_gemm_mma<128><<<gemm_blocks, 512, SM128>>>(nullptr, 0, g1, be1,
        wblk_ptr + 32768, wblk_ptr + 49152);
    k_agg128<<<agg_blocks, 256>>>(b2, nullptr, 256);

    // layer 3 (N = 64; BN finalize of layer-2 stats fused)
    k_gemm_mma<64><<<gemm_blocks, 512, SM64>>>(nullptr, 256, g2, be2,
        wblk_ptr + 65536, wblk_ptr + 73728);
    k_agg64<<<agg_blocks, 256>>>(b3, out);
}